// round 12
// baseline (speedup 1.0000x reference)
#include <cuda_runtime.h>
#include <cstdint>

#define E_DIM 288
#define B_SZ 4
#define N_SEQ 2048
#define H_NUM 8
#define D_HEAD 36
#define M_ROWS (B_SZ * N_SEQ)  // 8192

__device__ float g_q[M_ROWS * E_DIM];
__device__ float g_k[M_ROWS * E_DIM];
__device__ float g_v[M_ROWS * E_DIM];
__device__ float g_att[M_ROWS * E_DIM];

// ============================ helpers ============================
__device__ __forceinline__ uint32_t f2tf(float x) {
  uint32_t u;
  asm("cvt.rna.tf32.f32 %0, %1;" : "=r"(u) : "f"(x));
  return u;
}
__device__ __forceinline__ void mma8(float* c, uint32_t a0, uint32_t a1,
                                     uint32_t a2, uint32_t a3, uint32_t b0,
                                     uint32_t b1) {
  asm volatile(
      "mma.sync.aligned.m16n8k8.row.col.f32.tf32.tf32.f32 "
      "{%0,%1,%2,%3}, {%4,%5,%6,%7}, {%8,%9}, {%0,%1,%2,%3};"
      : "+f"(c[0]), "+f"(c[1]), "+f"(c[2]), "+f"(c[3])
      : "r"(a0), "r"(a1), "r"(a2), "r"(a3), "r"(b0), "r"(b1));
}

// ---------------------------------------------------------------------------
// tf32 HMMA flash attention (unchanged from R11)
// ---------------------------------------------------------------------------
__global__ __launch_bounds__(256, 2) void attn_mma_kernel(
    const float* __restrict__ Q, const float* __restrict__ K,
    const float* __restrict__ V, float* __restrict__ Oa) {
  __shared__ uint32_t Kh[2][64][36];  // [buf][j][d]
  __shared__ uint32_t Vsm[2][2560];   // [buf][n*320 + lane*10 + 2v + hi]

  const int t = threadIdx.x;
  const int wid = t >> 5;
  const int lane = t & 31;
  const int q = lane & 3;
  const int rg = lane >> 2;
  const int b = blockIdx.y >> 3, h = blockIdx.y & 7;
  const int q0 = blockIdx.x * 128;

  for (int i = t; i < 512; i += 256) {
    int bu = i >> 8, r = i & 255;
    int n = r >> 5, idx2 = r & 31;
    int L = 16 + (idx2 >> 1), hi = idx2 & 1;
    Vsm[bu][n * 320 + L * 10 + 8 + hi] = 0;
  }

  const float* qg = Q + ((size_t)(b * N_SEQ + q0 + wid * 16)) * E_DIM + h * D_HEAD;
  uint32_t qh[5][4];
#pragma unroll
  for (int s = 0; s < 5; s++) {
    int d0 = 8 * s + q;
    int d1 = d0 + 4;
    qh[s][0] = f2tf(qg[(size_t)rg * E_DIM + d0]);
    qh[s][1] = f2tf(qg[(size_t)(rg + 8) * E_DIM + d0]);
    qh[s][2] = (d1 < 36) ? f2tf(qg[(size_t)rg * E_DIM + d1]) : 0u;
    qh[s][3] = (d1 < 36) ? f2tf(qg[(size_t)(rg + 8) * E_DIM + d1]) : 0u;
  }

  int goff[3], koff[3], voff[3];
  bool act[3];
#pragma unroll
  for (int it = 0; it < 3; it++) {
    int idx = t + (it << 8);
    act[it] = idx < 576;
    int j = idx / 9;
    if (j > 63) j = 63;
    int f4 = idx - j * 9;
    int n = j >> 3, m = j & 7;
    int c0 = f4 * 4;
    int rg0 = c0 & 7, v0 = c0 >> 3;
    goff[it] = j * E_DIM + c0;
    koff[it] = j * 36 + c0;
    voff[it] = n * 320 + (rg0 * 4 + (m >> 1)) * 10 + v0 * 2 + (m & 1);
  }
  const float* kg = K + ((size_t)(b * N_SEQ)) * E_DIM + h * D_HEAD;
  const float* vg = V + ((size_t)(b * N_SEQ)) * E_DIM + h * D_HEAD;

  float O[5][4];
#pragma unroll
  for (int v = 0; v < 5; v++)
#pragma unroll
    for (int i = 0; i < 4; i++) O[v][i] = 0.f;
  float l0 = 0.f, l1 = 0.f;

  float4 kr[3], vr[3];
#pragma unroll
  for (int it = 0; it < 3; it++)
    if (act[it]) {
      kr[it] = *(const float4*)(kg + goff[it]);
      vr[it] = *(const float4*)(vg + goff[it]);
    }
#pragma unroll
  for (int it = 0; it < 3; it++)
    if (act[it]) {
      uint4 kt4 = {f2tf(kr[it].x), f2tf(kr[it].y), f2tf(kr[it].z), f2tf(kr[it].w)};
      *(uint4*)&Kh[0][0][koff[it]] = kt4;
      uint32_t* vd = &Vsm[0][0];
      vd[voff[it]] = f2tf(vr[it].x);
      vd[voff[it] + 40] = f2tf(vr[it].y);
      vd[voff[it] + 80] = f2tf(vr[it].z);
      vd[voff[it] + 120] = f2tf(vr[it].w);
    }
  __syncthreads();

  for (int kt = 0; kt < N_SEQ / 64; kt++) {
    const int buf = kt & 1;
    if (kt < N_SEQ / 64 - 1) {
      const float* kp = kg + (size_t)(kt + 1) * 64 * E_DIM;
      const float* vp = vg + (size_t)(kt + 1) * 64 * E_DIM;
#pragma unroll
      for (int it = 0; it < 3; it++)
        if (act[it]) {
          kr[it] = *(const float4*)(kp + goff[it]);
          vr[it] = *(const float4*)(vp + goff[it]);
        }
    }

    const uint32_t* Khb = &Kh[buf][0][0];
    const uint32_t* Vb = &Vsm[buf][0];
#pragma unroll
    for (int np = 0; np < 4; np++) {
      const int n0 = 2 * np, n1 = 2 * np + 1;
      float S0[4] = {0.f, 0.f, 0.f, 0.f};
      float S1[4] = {0.f, 0.f, 0.f, 0.f};
      const uint32_t* krow0 = Khb + (8 * n0 + rg) * 36;
      const uint32_t* krow1 = Khb + (8 * n1 + rg) * 36;
#pragma unroll
      for (int s = 0; s < 5; s++) {
        uint32_t b00 = krow0[8 * s + q];
        uint32_t b01 = (s < 4) ? krow0[8 * s + q + 4] : 0u;
        uint32_t b10 = krow1[8 * s + q];
        uint32_t b11 = (s < 4) ? krow1[8 * s + q + 4] : 0u;
        mma8(S0, qh[s][0], qh[s][1], qh[s][2], qh[s][3], b00, b01);
        mma8(S1, qh[s][0], qh[s][1], qh[s][2], qh[s][3], b10, b11);
      }
#pragma unroll
      for (int half = 0; half < 2; half++) {
        const float* S = half ? S1 : S0;
        const int n = half ? n1 : n0;
        float p0 = __expf(S[0]);
        float p1 = __expf(S[1]);
        float p2 = __expf(S[2]);
        float p3 = __expf(S[3]);
        l0 += p0 + p1;
        l1 += p2 + p3;
        uint32_t pa0 = f2tf(p0), pa1 = f2tf(p2), pa2 = f2tf(p1), pa3 = f2tf(p3);
        const uint32_t* vp = Vb + n * 320 + lane * 10;
#pragma unroll
        for (int v = 0; v < 5; v++) {
          uint2 bb = *(const uint2*)(vp + 2 * v);
          mma8(O[v], pa0, pa1, pa2, pa3, bb.x, bb.y);
        }
      }
    }

    if (kt < N_SEQ / 64 - 1) {
      uint32_t* kd = &Kh[buf ^ 1][0][0];
      uint32_t* vd = &Vsm[buf ^ 1][0];
#pragma unroll
      for (int it = 0; it < 3; it++)
        if (act[it]) {
          uint4 kt4 = {f2tf(kr[it].x), f2tf(kr[it].y), f2tf(kr[it].z),
                       f2tf(kr[it].w)};
          *(uint4*)(kd + koff[it]) = kt4;
          vd[voff[it]] = f2tf(vr[it].x);
          vd[voff[it] + 40] = f2tf(vr[it].y);
          vd[voff[it] + 80] = f2tf(vr[it].z);
          vd[voff[it] + 120] = f2tf(vr[it].w);
        }
    }
    __syncthreads();
  }

  l0 += __shfl_xor_sync(0xffffffffu, l0, 1);
  l0 += __shfl_xor_sync(0xffffffffu, l0, 2);
  l1 += __shfl_xor_sync(0xffffffffu, l1, 1);
  l1 += __shfl_xor_sync(0xffffffffu, l1, 2);
  float inv0 = 1.f / l0, inv1 = 1.f / l1;

  const int row = q0 + wid * 16 + rg;
  float* ob0 = Oa + (size_t)(b * N_SEQ + row) * E_DIM + h * D_HEAD;
  float* ob1 = Oa + (size_t)(b * N_SEQ + row + 8) * E_DIM + h * D_HEAD;
#pragma unroll
  for (int v = 0; v < 5; v++) {
    int col = 8 * v + 2 * q;
    if (col < 36) {
      *(float2*)(ob0 + col) = make_float2(O[v][0] * inv0, O[v][1] * inv0);
      *(float2*)(ob1 + col) = make_float2(O[v][2] * inv1, O[v][3] * inv1);
    }
  }
}

// ---------------------------------------------------------------------------
// GEMM body R12: SINGLE-term tf32 (C = Ah*Wh). W staged tf32, A staged raw.
// Double-buffered; occupancy 6 CTAs/SM.
// ---------------------------------------------------------------------------
#define NKT (E_DIM / 16)  // 18

__device__ __forceinline__ void gemm_body(const float* __restrict__ A,
                                          const float* __restrict__ W,
                                          const float* __restrict__ bias,
                                          float* __restrict__ C, float scale,
                                          int row_blk, int col_blk) {
  __shared__ uint32_t Wh[2][16][104];
  __shared__ float As[2][64][20];

  const int t = threadIdx.x;
  const int wid = t >> 5;
  const int lane = t & 31;
  const int q = lane & 3;
  const int rg = lane >> 2;
  const int warp_m = wid & 1;
  const int warp_n = wid >> 1;
  const int ncol0 = warp_n * 48;

  int wg_off[3], ws_off[3];
#pragma unroll
  for (int i = 0; i < 3; i++) {
    int idx = t + i * 128;
    int kk = idx / 24, n4 = idx - kk * 24;
    wg_off[i] = kk * E_DIM + n4 * 4;
    ws_off[i] = kk * 104 + n4 * 4;
  }
  int ag_off[2], as_off[2];
#pragma unroll
  for (int i = 0; i < 2; i++) {
    int idx = t + i * 128;
    int row = idx >> 2, k4 = idx & 3;
    ag_off[i] = row * E_DIM + k4 * 4;
    as_off[i] = row * 20 + k4 * 4;
  }
  const float* Wg = W + col_blk;
  const float* Ag = A + (size_t)row_blk * E_DIM;

  float acc[2][6][4];
#pragma unroll
  for (int mb = 0; mb < 2; mb++)
#pragma unroll
    for (int nb = 0; nb < 6; nb++)
#pragma unroll
      for (int i = 0; i < 4; i++) acc[mb][nb][i] = 0.f;

  float4 wreg[3], areg[2];
#pragma unroll
  for (int i = 0; i < 3; i++) wreg[i] = *(const float4*)(Wg + wg_off[i]);
#pragma unroll
  for (int i = 0; i < 2; i++) areg[i] = *(const float4*)(Ag + ag_off[i]);
#pragma unroll
  for (int i = 0; i < 3; i++) {
    uint4 hi = {f2tf(wreg[i].x), f2tf(wreg[i].y), f2tf(wreg[i].z), f2tf(wreg[i].w)};
    *(uint4*)&Wh[0][0][ws_off[i]] = hi;
  }
#pragma unroll
  for (int i = 0; i < 2; i++) *(float4*)&As[0][0][as_off[i]] = areg[i];
  __syncthreads();

  for (int kt = 0; kt < NKT; kt++) {
    const int buf = kt & 1;
    if (kt < NKT - 1) {
      const int k0 = (kt + 1) * 16;
#pragma unroll
      for (int i = 0; i < 3; i++)
        wreg[i] = *(const float4*)(Wg + (size_t)k0 * E_DIM + wg_off[i]);
#pragma unroll
      for (int i = 0; i < 2; i++)
        areg[i] = *(const float4*)(Ag + k0 + ag_off[i]);
    }

#pragma unroll
    for (int s = 0; s < 2; s++) {
      uint32_t ah[2][4];
#pragma unroll
      for (int mb = 0; mb < 2; mb++) {
        const int r0 = warp_m * 32 + mb * 16;
        ah[mb][0] = f2tf(As[buf][r0 + rg][8 * s + q]);
        ah[mb][1] = f2tf(As[buf][r0 + rg + 8][8 * s + q]);
        ah[mb][2] = f2tf(As[buf][r0 + rg][8 * s + q + 4]);
        ah[mb][3] = f2tf(As[buf][r0 + rg + 8][8 * s + q + 4]);
      }
#pragma unroll
      for (int nb = 0; nb < 6; nb++) {
        const int n = ncol0 + nb * 8 + rg;
        uint32_t bh0 = Wh[buf][8 * s + q][n];
        uint32_t bh1 = Wh[buf][8 * s + q + 4][n];
#pragma unroll
        for (int mb = 0; mb < 2; mb++) {
          mma8(acc[mb][nb], ah[mb][0], ah[mb][1], ah[mb][2], ah[mb][3], bh0, bh1);
        }
      }
    }

    if (kt < NKT - 1) {
#pragma unroll
      for (int i = 0; i < 3; i++) {
        uint4 hi = {f2tf(wreg[i].x), f2tf(wreg[i].y), f2tf(wreg[i].z),
                    f2tf(wreg[i].w)};
        *(uint4*)&Wh[buf ^ 1][0][ws_off[i]] = hi;
      }
#pragma unroll
      for (int i = 0; i < 2; i++)
        *(float4*)&As[buf ^ 1][0][as_off[i]] = areg[i];
    }
    __syncthreads();
  }

#pragma unroll
  for (int mb = 0; mb < 2; mb++) {
    const int r0 = row_blk + warp_m * 32 + mb * 16 + rg;
#pragma unroll
    for (int nb = 0; nb < 6; nb++) {
      const int c = col_blk + ncol0 + nb * 8 + 2 * q;
      const float b0 = bias[c], b1 = bias[c + 1];
      *(float2*)(C + (size_t)r0 * E_DIM + c) =
          make_float2((acc[mb][nb][0] + b0) * scale,
                      (acc[mb][nb][1] + b1) * scale);
      *(float2*)(C + (size_t)(r0 + 8) * E_DIM + c) =
          make_float2((acc[mb][nb][2] + b0) * scale,
                      (acc[mb][nb][3] + b1) * scale);
    }
  }
}

__global__ __launch_bounds__(128, 6) void gemm_qkv_kernel(
    const float* __restrict__ Aq, const float* __restrict__ Ak,
    const float* __restrict__ Av, const float* __restrict__ Wq,
    const float* __restrict__ Wk, const float* __restrict__ Wv,
    const float* __restrict__ bq, const float* __restrict__ bk,
    const float* __restrict__ bv, float* __restrict__ Cq,
    float* __restrict__ Ck, float* __restrict__ Cv, float scaling) {
  const int z = blockIdx.z;
  const float* A = (z == 0) ? Aq : (z == 1) ? Ak : Av;
  const float* W = (z == 0) ? Wq : (z == 1) ? Wk : Wv;
  const float* bias = (z == 0) ? bq : (z == 1) ? bk : bv;
  float* C = (z == 0) ? Cq : (z == 1) ? Ck : Cv;
  const float scale = (z == 0) ? scaling : 1.0f;
  gemm_body(A, W, bias, C, scale, blockIdx.y * 64, blockIdx.x * 96);
}

__global__ __launch_bounds__(128, 6) void gemm_mma_kernel(
    const float* __restrict__ A, const float* __restrict__ W,
    const float* __restrict__ bias, float* __restrict__ C, float scale) {
  gemm_body(A, W, bias, C, scale, blockIdx.y * 64, blockIdx.x * 96);
}

// ---------------------------------------------------------------------------
extern "C" void kernel_launch(void* const* d_in, const int* in_sizes, int n_in,
                              void* d_out, int out_size) {
  const float* query = (const float*)d_in[0];
  const float* key   = (const float*)d_in[1];
  const float* value = (const float*)d_in[2];
  const float* Wq = (const float*)d_in[3];
  const float* bq = (const float*)d_in[4];
  const float* Wk = (const float*)d_in[5];
  const float* bk = (const float*)d_in[6];
  const float* Wv = (const float*)d_in[7];
  const float* bv = (const float*)d_in[8];
  const float* Wo = (const float*)d_in[9];
  const float* bo = (const float*)d_in[10];
  float* out = (float*)d_out;

  float *gq, *gk, *gv, *ga;
  cudaGetSymbolAddress((void**)&gq, g_q);
  cudaGetSymbolAddress((void**)&gk, g_k);
  cudaGetSymbolAddress((void**)&gv, g_v);
  cudaGetSymbolAddress((void**)&ga, g_att);

  const float scaling = 1.0f / 6.0f;  // D=36 -> 36^-0.5
  dim3 qkvGrid(E_DIM / 96, M_ROWS / 64, 3);
  dim3 gGrid(E_DIM / 96, M_ROWS / 64);
  dim3 gBlk(128);

  gemm_qkv_kernel<<<qkvGrid, gBlk>>>(query, key, value, Wq, Wk, Wv, bq, bk, bv,
                                     gq, gk, gv, scaling);

  attn_mma_kernel<<<dim3(N_SEQ / 128, B_SZ * H_NUM), 256>>>(gq, gk, gv, ga);

  gemm_mma_kernel<<<gGrid, gBlk>>>(ga, Wo, bo, out, 1.0f);
}

// round 13
// speedup vs baseline: 1.2305x; 1.2305x over previous
#include <cuda_runtime.h>
#include <cstdint>

#define E_DIM 288
#define B_SZ 4
#define N_SEQ 2048
#define H_NUM 8
#define D_HEAD 36
#define M_ROWS (B_SZ * N_SEQ)  // 8192

__device__ float g_q[M_ROWS * E_DIM];
__device__ float g_k[M_ROWS * E_DIM];
__device__ float g_v[M_ROWS * E_DIM];
__device__ float g_att[M_ROWS * E_DIM];

// ============================ helpers ============================
__device__ __forceinline__ uint32_t f2tf(float x) {
  uint32_t u;
  asm("cvt.rna.tf32.f32 %0, %1;" : "=r"(u) : "f"(x));
  return u;
}
__device__ __forceinline__ void mma8(float* c, uint32_t a0, uint32_t a1,
                                     uint32_t a2, uint32_t a3, uint32_t b0,
                                     uint32_t b1) {
  asm volatile(
      "mma.sync.aligned.m16n8k8.row.col.f32.tf32.tf32.f32 "
      "{%0,%1,%2,%3}, {%4,%5,%6,%7}, {%8,%9}, {%0,%1,%2,%3};"
      : "+f"(c[0]), "+f"(c[1]), "+f"(c[2]), "+f"(c[3])
      : "r"(a0), "r"(a1), "r"(a2), "r"(a3), "r"(b0), "r"(b1));
}
#define CP_ASYNC16(dst32, src) \
  asm volatile("cp.async.cg.shared.global [%0], [%1], 16;" :: "r"(dst32), "l"(src))
#define CP_COMMIT() asm volatile("cp.async.commit_group;" ::: "memory")
#define CP_WAIT(n) asm volatile("cp.async.wait_group %0;" :: "n"(n) : "memory")

// ---------------------------------------------------------------------------
// tf32 HMMA flash attention (unchanged from R11 — best validated config)
// ---------------------------------------------------------------------------
__global__ __launch_bounds__(256, 2) void attn_mma_kernel(
    const float* __restrict__ Q, const float* __restrict__ K,
    const float* __restrict__ V, float* __restrict__ Oa) {
  __shared__ uint32_t Kh[2][64][36];  // [buf][j][d]
  __shared__ uint32_t Vsm[2][2560];   // [buf][n*320 + lane*10 + 2v + hi]

  const int t = threadIdx.x;
  const int wid = t >> 5;
  const int lane = t & 31;
  const int q = lane & 3;
  const int rg = lane >> 2;
  const int b = blockIdx.y >> 3, h = blockIdx.y & 7;
  const int q0 = blockIdx.x * 128;

  for (int i = t; i < 512; i += 256) {
    int bu = i >> 8, r = i & 255;
    int n = r >> 5, idx2 = r & 31;
    int L = 16 + (idx2 >> 1), hi = idx2 & 1;
    Vsm[bu][n * 320 + L * 10 + 8 + hi] = 0;
  }

  const float* qg = Q + ((size_t)(b * N_SEQ + q0 + wid * 16)) * E_DIM + h * D_HEAD;
  uint32_t qh[5][4];
#pragma unroll
  for (int s = 0; s < 5; s++) {
    int d0 = 8 * s + q;
    int d1 = d0 + 4;
    qh[s][0] = f2tf(qg[(size_t)rg * E_DIM + d0]);
    qh[s][1] = f2tf(qg[(size_t)(rg + 8) * E_DIM + d0]);
    qh[s][2] = (d1 < 36) ? f2tf(qg[(size_t)rg * E_DIM + d1]) : 0u;
    qh[s][3] = (d1 < 36) ? f2tf(qg[(size_t)(rg + 8) * E_DIM + d1]) : 0u;
  }

  int goff[3], koff[3], voff[3];
  bool act[3];
#pragma unroll
  for (int it = 0; it < 3; it++) {
    int idx = t + (it << 8);
    act[it] = idx < 576;
    int j = idx / 9;
    if (j > 63) j = 63;
    int f4 = idx - j * 9;
    int n = j >> 3, m = j & 7;
    int c0 = f4 * 4;
    int rg0 = c0 & 7, v0 = c0 >> 3;
    goff[it] = j * E_DIM + c0;
    koff[it] = j * 36 + c0;
    voff[it] = n * 320 + (rg0 * 4 + (m >> 1)) * 10 + v0 * 2 + (m & 1);
  }
  const float* kg = K + ((size_t)(b * N_SEQ)) * E_DIM + h * D_HEAD;
  const float* vg = V + ((size_t)(b * N_SEQ)) * E_DIM + h * D_HEAD;

  float O[5][4];
#pragma unroll
  for (int v = 0; v < 5; v++)
#pragma unroll
    for (int i = 0; i < 4; i++) O[v][i] = 0.f;
  float l0 = 0.f, l1 = 0.f;

  float4 kr[3], vr[3];
#pragma unroll
  for (int it = 0; it < 3; it++)
    if (act[it]) {
      kr[it] = *(const float4*)(kg + goff[it]);
      vr[it] = *(const float4*)(vg + goff[it]);
    }
#pragma unroll
  for (int it = 0; it < 3; it++)
    if (act[it]) {
      uint4 kt4 = {f2tf(kr[it].x), f2tf(kr[it].y), f2tf(kr[it].z), f2tf(kr[it].w)};
      *(uint4*)&Kh[0][0][koff[it]] = kt4;
      uint32_t* vd = &Vsm[0][0];
      vd[voff[it]] = f2tf(vr[it].x);
      vd[voff[it] + 40] = f2tf(vr[it].y);
      vd[voff[it] + 80] = f2tf(vr[it].z);
      vd[voff[it] + 120] = f2tf(vr[it].w);
    }
  __syncthreads();

  for (int kt = 0; kt < N_SEQ / 64; kt++) {
    const int buf = kt & 1;
    if (kt < N_SEQ / 64 - 1) {
      const float* kp = kg + (size_t)(kt + 1) * 64 * E_DIM;
      const float* vp = vg + (size_t)(kt + 1) * 64 * E_DIM;
#pragma unroll
      for (int it = 0; it < 3; it++)
        if (act[it]) {
          kr[it] = *(const float4*)(kp + goff[it]);
          vr[it] = *(const float4*)(vp + goff[it]);
        }
    }

    const uint32_t* Khb = &Kh[buf][0][0];
    const uint32_t* Vb = &Vsm[buf][0];
#pragma unroll
    for (int np = 0; np < 4; np++) {
      const int n0 = 2 * np, n1 = 2 * np + 1;
      float S0[4] = {0.f, 0.f, 0.f, 0.f};
      float S1[4] = {0.f, 0.f, 0.f, 0.f};
      const uint32_t* krow0 = Khb + (8 * n0 + rg) * 36;
      const uint32_t* krow1 = Khb + (8 * n1 + rg) * 36;
#pragma unroll
      for (int s = 0; s < 5; s++) {
        uint32_t b00 = krow0[8 * s + q];
        uint32_t b01 = (s < 4) ? krow0[8 * s + q + 4] : 0u;
        uint32_t b10 = krow1[8 * s + q];
        uint32_t b11 = (s < 4) ? krow1[8 * s + q + 4] : 0u;
        mma8(S0, qh[s][0], qh[s][1], qh[s][2], qh[s][3], b00, b01);
        mma8(S1, qh[s][0], qh[s][1], qh[s][2], qh[s][3], b10, b11);
      }
#pragma unroll
      for (int half = 0; half < 2; half++) {
        const float* S = half ? S1 : S0;
        const int n = half ? n1 : n0;
        float p0 = __expf(S[0]);
        float p1 = __expf(S[1]);
        float p2 = __expf(S[2]);
        float p3 = __expf(S[3]);
        l0 += p0 + p1;
        l1 += p2 + p3;
        uint32_t pa0 = f2tf(p0), pa1 = f2tf(p2), pa2 = f2tf(p1), pa3 = f2tf(p3);
        const uint32_t* vp = Vb + n * 320 + lane * 10;
#pragma unroll
        for (int v = 0; v < 5; v++) {
          uint2 bb = *(const uint2*)(vp + 2 * v);
          mma8(O[v], pa0, pa1, pa2, pa3, bb.x, bb.y);
        }
      }
    }

    if (kt < N_SEQ / 64 - 1) {
      uint32_t* kd = &Kh[buf ^ 1][0][0];
      uint32_t* vd = &Vsm[buf ^ 1][0];
#pragma unroll
      for (int it = 0; it < 3; it++)
        if (act[it]) {
          uint4 kt4 = {f2tf(kr[it].x), f2tf(kr[it].y), f2tf(kr[it].z),
                       f2tf(kr[it].w)};
          *(uint4*)(kd + koff[it]) = kt4;
          vd[voff[it]] = f2tf(vr[it].x);
          vd[voff[it] + 40] = f2tf(vr[it].y);
          vd[voff[it] + 80] = f2tf(vr[it].z);
          vd[voff[it] + 120] = f2tf(vr[it].w);
        }
    }
    __syncthreads();
  }

  l0 += __shfl_xor_sync(0xffffffffu, l0, 1);
  l0 += __shfl_xor_sync(0xffffffffu, l0, 2);
  l1 += __shfl_xor_sync(0xffffffffu, l1, 1);
  l1 += __shfl_xor_sync(0xffffffffu, l1, 2);
  float inv0 = 1.f / l0, inv1 = 1.f / l1;

  const int row = q0 + wid * 16 + rg;
  float* ob0 = Oa + (size_t)(b * N_SEQ + row) * E_DIM + h * D_HEAD;
  float* ob1 = Oa + (size_t)(b * N_SEQ + row + 8) * E_DIM + h * D_HEAD;
#pragma unroll
  for (int v = 0; v < 5; v++) {
    int col = 8 * v + 2 * q;
    if (col < 36) {
      *(float2*)(ob0 + col) = make_float2(O[v][0] * inv0, O[v][1] * inv0);
      *(float2*)(ob1 + col) = make_float2(O[v][2] * inv1, O[v][3] * inv1);
    }
  }
}

// ---------------------------------------------------------------------------
// GEMM body R13: single-term tf32, 3-stage cp.async pipeline.
// Raw fp32 W (stride 104, conflict-free) and A (stride 20) in smem;
// tf32 conversion at fragment read. Graded wait_group at pipeline tail.
// ---------------------------------------------------------------------------
#define NKT (E_DIM / 16)  // 18

__device__ __forceinline__ void gemm_body(const float* __restrict__ A,
                                          const float* __restrict__ W,
                                          const float* __restrict__ bias,
                                          float* __restrict__ C, float scale,
                                          int row_blk, int col_blk) {
  __shared__ float Wsm[3][16][104];
  __shared__ float As[3][64][20];

  const int t = threadIdx.x;
  const int wid = t >> 5;
  const int lane = t & 31;
  const int q = lane & 3;
  const int rg = lane >> 2;
  const int warp_m = wid & 1;
  const int warp_n = wid >> 1;
  const int ncol0 = warp_n * 48;

  // per-thread copy slots
  int wg_off[3], ws_off[3];
#pragma unroll
  for (int i = 0; i < 3; i++) {
    int idx = t + i * 128;  // 0..383
    int kk = idx / 24, n4 = idx - kk * 24;
    wg_off[i] = kk * E_DIM + n4 * 4;
    ws_off[i] = kk * 104 + n4 * 4;
  }
  int ag_off[2], as_off[2];
#pragma unroll
  for (int i = 0; i < 2; i++) {
    int idx = t + i * 128;  // 0..255
    int row = idx >> 2, k4 = idx & 3;
    ag_off[i] = row * E_DIM + k4 * 4;
    as_off[i] = row * 20 + k4 * 4;
  }
  const float* Wg = W + col_blk;
  const float* Ag = A + (size_t)row_blk * E_DIM;
  const uint32_t wbase = (uint32_t)__cvta_generic_to_shared(&Wsm[0][0][0]);
  const uint32_t abase = (uint32_t)__cvta_generic_to_shared(&As[0][0][0]);

  float acc[2][6][4];
#pragma unroll
  for (int mb = 0; mb < 2; mb++)
#pragma unroll
    for (int nb = 0; nb < 6; nb++)
#pragma unroll
      for (int i = 0; i < 4; i++) acc[mb][nb][i] = 0.f;

  // prologue: issue stages 0,1,2
#pragma unroll
  for (int st = 0; st < 3; st++) {
    const int k0 = st * 16;
#pragma unroll
    for (int i = 0; i < 3; i++)
      CP_ASYNC16(wbase + (uint32_t)(st * 16 * 104 + ws_off[i]) * 4u,
                 Wg + (size_t)k0 * E_DIM + wg_off[i]);
#pragma unroll
    for (int i = 0; i < 2; i++)
      CP_ASYNC16(abase + (uint32_t)(st * 64 * 20 + as_off[i]) * 4u,
                 Ag + k0 + ag_off[i]);
    CP_COMMIT();
  }

  for (int kt = 0; kt < NKT; kt++) {
    if (kt < NKT - 2) {
      CP_WAIT(2);
    } else if (kt == NKT - 2) {
      CP_WAIT(1);
    } else {
      CP_WAIT(0);
    }
    __syncthreads();

    const int buf = kt % 3;
    const float* Wb = &Wsm[buf][0][0];
    const float* Ab = &As[buf][0][0];
#pragma unroll
    for (int s = 0; s < 2; s++) {
      uint32_t ah[2][4];
#pragma unroll
      for (int mb = 0; mb < 2; mb++) {
        const int r0 = warp_m * 32 + mb * 16;
        ah[mb][0] = f2tf(Ab[(r0 + rg) * 20 + 8 * s + q]);
        ah[mb][1] = f2tf(Ab[(r0 + rg + 8) * 20 + 8 * s + q]);
        ah[mb][2] = f2tf(Ab[(r0 + rg) * 20 + 8 * s + q + 4]);
        ah[mb][3] = f2tf(Ab[(r0 + rg + 8) * 20 + 8 * s + q + 4]);
      }
#pragma unroll
      for (int nb = 0; nb < 6; nb++) {
        const int n = ncol0 + nb * 8 + rg;
        uint32_t bh0 = f2tf(Wb[(8 * s + q) * 104 + n]);
        uint32_t bh1 = f2tf(Wb[(8 * s + q + 4) * 104 + n]);
#pragma unroll
        for (int mb = 0; mb < 2; mb++) {
          mma8(acc[mb][nb], ah[mb][0], ah[mb][1], ah[mb][2], ah[mb][3], bh0, bh1);
        }
      }
    }
    __syncthreads();

    if (kt + 3 < NKT) {
      const int k0 = (kt + 3) * 16;
#pragma unroll
      for (int i = 0; i < 3; i++)
        CP_ASYNC16(wbase + (uint32_t)(buf * 16 * 104 + ws_off[i]) * 4u,
                   Wg + (size_t)k0 * E_DIM + wg_off[i]);
#pragma unroll
      for (int i = 0; i < 2; i++)
        CP_ASYNC16(abase + (uint32_t)(buf * 64 * 20 + as_off[i]) * 4u,
                   Ag + k0 + ag_off[i]);
      CP_COMMIT();
    }
  }

#pragma unroll
  for (int mb = 0; mb < 2; mb++) {
    const int r0 = row_blk + warp_m * 32 + mb * 16 + rg;
#pragma unroll
    for (int nb = 0; nb < 6; nb++) {
      const int c = col_blk + ncol0 + nb * 8 + 2 * q;
      const float b0 = bias[c], b1 = bias[c + 1];
      *(float2*)(C + (size_t)r0 * E_DIM + c) =
          make_float2((acc[mb][nb][0] + b0) * scale,
                      (acc[mb][nb][1] + b1) * scale);
      *(float2*)(C + (size_t)(r0 + 8) * E_DIM + c) =
          make_float2((acc[mb][nb][2] + b0) * scale,
                      (acc[mb][nb][3] + b1) * scale);
    }
  }
}

__global__ __launch_bounds__(128, 6) void gemm_qkv_kernel(
    const float* __restrict__ Aq, const float* __restrict__ Ak,
    const float* __restrict__ Av, const float* __restrict__ Wq,
    const float* __restrict__ Wk, const float* __restrict__ Wv,
    const float* __restrict__ bq, const float* __restrict__ bk,
    const float* __restrict__ bv, float* __restrict__ Cq,
    float* __restrict__ Ck, float* __restrict__ Cv, float scaling) {
  const int z = blockIdx.z;
  const float* A = (z == 0) ? Aq : (z == 1) ? Ak : Av;
  const float* W = (z == 0) ? Wq : (z == 1) ? Wk : Wv;
  const float* bias = (z == 0) ? bq : (z == 1) ? bk : bv;
  float* C = (z == 0) ? Cq : (z == 1) ? Ck : Cv;
  const float scale = (z == 0) ? scaling : 1.0f;
  gemm_body(A, W, bias, C, scale, blockIdx.y * 64, blockIdx.x * 96);
}

__global__ __launch_bounds__(128, 6) void gemm_mma_kernel(
    const float* __restrict__ A, const float* __restrict__ W,
    const float* __restrict__ bias, float* __restrict__ C, float scale) {
  gemm_body(A, W, bias, C, scale, blockIdx.y * 64, blockIdx.x * 96);
}

// ---------------------------------------------------------------------------
extern "C" void kernel_launch(void* const* d_in, const int* in_sizes, int n_in,
                              void* d_out, int out_size) {
  const float* query = (const float*)d_in[0];
  const float* key   = (const float*)d_in[1];
  const float* value = (const float*)d_in[2];
  const float* Wq = (const float*)d_in[3];
  const float* bq = (const float*)d_in[4];
  const float* Wk = (const float*)d_in[5];
  const float* bk = (const float*)d_in[6];
  const float* Wv = (const float*)d_in[7];
  const float* bv = (const float*)d_in[8];
  const float* Wo = (const float*)d_in[9];
  const float* bo = (const float*)d_in[10];
  float* out = (float*)d_out;

  float *gq, *gk, *gv, *ga;
  cudaGetSymbolAddress((void**)&gq, g_q);
  cudaGetSymbolAddress((void**)&gk, g_k);
  cudaGetSymbolAddress((void**)&gv, g_v);
  cudaGetSymbolAddress((void**)&ga, g_att);

  const float scaling = 1.0f / 6.0f;  // D=36 -> 36^-0.5
  dim3 qkvGrid(E_DIM / 96, M_ROWS / 64, 3);
  dim3 gGrid(E_DIM / 96, M_ROWS / 64);
  dim3 gBlk(128);

  gemm_qkv_kernel<<<qkvGrid, gBlk>>>(query, key, value, Wq, Wk, Wv, bq, bk, bv,
                                     gq, gk, gv, scaling);

  attn_mma_kernel<<<dim3(N_SEQ / 128, B_SZ * H_NUM), 256>>>(gq, gk, gv, ga);

  gemm_mma_kernel<<<gGrid, gBlk>>>(ga, Wo, bo, out, 1.0f);
}